// round 7
// baseline (speedup 1.0000x reference)
#include <cuda_runtime.h>
#include <cuda_bf16.h>

#define N_NODES 50000
#define N_EDGES 800000
#define IN_DIM  64
#define HID_DIM 128
#define OUT_DIM 64
#define CAP     128   // per-node bucket capacity (max in-degree ~35 for this input)

typedef unsigned long long u64;

// ---------------- packed f32x2 helpers (Blackwell FFMA2) ----------------
__device__ __forceinline__ u64 pk(float x, float y) {
    u64 r; asm("mov.b64 %0, {%1, %2};" : "=l"(r) : "f"(x), "f"(y)); return r;
}
__device__ __forceinline__ u64 dup2(float x) {
    u64 r; asm("mov.b64 %0, {%1, %2};" : "=l"(r) : "f"(x), "f"(x)); return r;
}
__device__ __forceinline__ void fma2(u64& d, u64 a, u64 b) {
    asm("fma.rn.f32x2 %0, %1, %2, %3;" : "=l"(d) : "l"(a), "l"(b), "l"(d));
}
__device__ __forceinline__ float2 unpk(u64 a) {
    float2 f; asm("mov.b64 {%0, %1}, %2;" : "=f"(f.x), "=f"(f.y) : "l"(a)); return f;
}

// ---------------- scratch ----------------
__device__ __align__(16) float g_az[N_NODES * IN_DIM];
__device__ __align__(16) float g_h [N_NODES * HID_DIM];
__device__ __align__(16) float g_hw[N_NODES * OUT_DIM];
__device__ float g_dinv[N_NODES];
__device__ int   g_cnt[N_NODES];
__device__ int   g_esrc[N_NODES * CAP];   // padded per-dst buckets

// ---------------- init ----------------
__global__ void k_init() {
    int i = blockIdx.x * blockDim.x + threadIdx.x;
    if (i < N_NODES) g_cnt[i] = 0;
}

// one pass: count + scatter (single atomic per edge)
__global__ void k_scatter(const int* __restrict__ ei) {
    int e = blockIdx.x * blockDim.x + threadIdx.x;
    if (e < N_EDGES) {
        int s = ei[e];
        int d = ei[N_EDGES + e];
        int pos = atomicAdd(&g_cnt[d], 1);
        if (pos < CAP) g_esrc[d * CAP + pos] = s;
    }
}

__global__ void k_dinv() {
    int i = blockIdx.x * blockDim.x + threadIdx.x;
    if (i < N_NODES) g_dinv[i] = rsqrtf((float)(g_cnt[i] + 1));  // +1 self-loop
}

// ---------------- gather-accumulate body (shared by both agg kernels) ----------------
__device__ __forceinline__ u64 agg_gather(const float* __restrict__ src,
                                          int beg, int end, float di,
                                          int lane, u64 acc) {
    int e = beg;
    for (; e + 8 <= end; e += 8) {
        int id[8]; u64 wv[8], vv[8];
        #pragma unroll
        for (int k = 0; k < 8; k++) id[k] = __ldg(&g_esrc[e + k]);
        #pragma unroll
        for (int k = 0; k < 8; k++) wv[k] = dup2(__ldg(&g_dinv[id[k]]) * di);
        #pragma unroll
        for (int k = 0; k < 8; k++) vv[k] = ((const u64*)src)[(size_t)id[k] * 32 + lane];
        #pragma unroll
        for (int k = 0; k < 8; k++) fma2(acc, wv[k], vv[k]);
    }
    for (; e + 4 <= end; e += 4) {
        int id[4]; u64 wv[4], vv[4];
        #pragma unroll
        for (int k = 0; k < 4; k++) id[k] = __ldg(&g_esrc[e + k]);
        #pragma unroll
        for (int k = 0; k < 4; k++) wv[k] = dup2(__ldg(&g_dinv[id[k]]) * di);
        #pragma unroll
        for (int k = 0; k < 4; k++) vv[k] = ((const u64*)src)[(size_t)id[k] * 32 + lane];
        #pragma unroll
        for (int k = 0; k < 4; k++) fma2(acc, wv[k], vv[k]);
    }
    for (; e < end; e++) {
        int s = __ldg(&g_esrc[e]);
        u64 wv = dup2(__ldg(&g_dinv[s]) * di);
        fma2(acc, wv, ((const u64*)src)[(size_t)s * 32 + lane]);
    }
    return acc;
}

// ---------------- Aggregation 0: az = A_norm @ z ----------------
__global__ __launch_bounds__(256) void k_aggz(const float* __restrict__ z) {
    int gw   = (blockIdx.x * blockDim.x + threadIdx.x) >> 5;
    int lane = threadIdx.x & 31;
    if (gw >= N_NODES) return;
    float di = g_dinv[gw];
    int deg = g_cnt[gw]; if (deg > CAP) deg = CAP;
    u64 acc = 0;
    fma2(acc, dup2(di * di), ((const u64*)z)[gw * 32 + lane]);
    acc = agg_gather(z, gw * CAP, gw * CAP + deg, di, lane, acc);
    ((u64*)g_az)[gw * 32 + lane] = acc;
}

// ---------------- GEMM 1: h = relu(az @ W1 + b1), 8 nodes per warp ----------------
__global__ __launch_bounds__(128) void k_gemm1(const float* __restrict__ W1,
                                               const float* __restrict__ b1) {
    __shared__ u64 sW[32 * 128];                       // 32 KB
    __shared__ __align__(16) float sX[4][8][IN_DIM];   // 8 KB
    int lane = threadIdx.x & 31;
    int w    = threadIdx.x >> 5;
    for (int idx = threadIdx.x; idx < 32 * 128; idx += 128) {
        int t = idx >> 7, j = idx & 127;
        sW[idx] = pk(W1[(2 * t) * 128 + j], W1[(2 * t + 1) * 128 + j]);
    }
    __syncthreads();
    int c0 = 2 * lane;
    float2 bA = *(const float2*)&b1[c0];
    float2 bB = *(const float2*)&b1[c0 + 64];

    int warpId = blockIdx.x * 4 + w;
    int nWarps = gridDim.x * 4;
    for (int base = warpId * 8; base < N_NODES; base += nWarps * 8) {
        #pragma unroll
        for (int q = 0; q < 4; q++) {
            int idx = lane + 32 * q;
            int n = idx >> 4, r = idx & 15;
            ((float4*)sX[w][n])[r] = ((const float4*)(g_az + (size_t)(base + n) * IN_DIM))[r];
        }
        __syncwarp();
        u64 aA0[8], aA1[8], aB0[8], aB1[8];
        #pragma unroll
        for (int n = 0; n < 8; n++) {
            aA0[n] = pk(bA.x, 0.f); aA1[n] = pk(bA.y, 0.f);
            aB0[n] = pk(bB.x, 0.f); aB1[n] = pk(bB.y, 0.f);
        }
        #pragma unroll 4
        for (int t = 0; t < 32; t++) {
            ulonglong2 wA = *(const ulonglong2*)&sW[t * 128 + c0];
            ulonglong2 wB = *(const ulonglong2*)&sW[t * 128 + c0 + 64];
            #pragma unroll
            for (int n = 0; n < 8; n++) {
                u64 xp = *(const u64*)&sX[w][n][2 * t];
                fma2(aA0[n], xp, wA.x); fma2(aA1[n], xp, wA.y);
                fma2(aB0[n], xp, wB.x); fma2(aB1[n], xp, wB.y);
            }
        }
        #pragma unroll
        for (int n = 0; n < 8; n++) {
            float2 f0 = unpk(aA0[n]), f1 = unpk(aA1[n]);
            float2 f2 = unpk(aB0[n]), f3 = unpk(aB1[n]);
            float* hrow = g_h + (size_t)(base + n) * HID_DIM;
            ((float2*)hrow)[lane] =
                make_float2(fmaxf(f0.x + f0.y, 0.f), fmaxf(f1.x + f1.y, 0.f));
            ((float2*)(hrow + 64))[lane] =
                make_float2(fmaxf(f2.x + f2.y, 0.f), fmaxf(f3.x + f3.y, 0.f));
        }
        __syncwarp();
    }
}

// ---------------- GEMM 2: hw = h @ W2, 8 nodes per warp ----------------
__global__ __launch_bounds__(128) void k_gemm2(const float* __restrict__ W2) {
    __shared__ u64 sW[64 * 64];                         // 32 KB
    __shared__ __align__(16) float sX[4][8][HID_DIM];   // 16 KB
    int lane = threadIdx.x & 31;
    int w    = threadIdx.x >> 5;
    for (int idx = threadIdx.x; idx < 64 * 64; idx += 128) {
        int t = idx >> 6, j = idx & 63;
        sW[idx] = pk(W2[(2 * t) * 64 + j], W2[(2 * t + 1) * 64 + j]);
    }
    __syncthreads();
    int c0 = 2 * lane;

    int warpId = blockIdx.x * 4 + w;
    int nWarps = gridDim.x * 4;
    for (int base = warpId * 8; base < N_NODES; base += nWarps * 8) {
        #pragma unroll
        for (int q = 0; q < 8; q++) {
            int idx = lane + 32 * q;
            int n = idx >> 5, r = idx & 31;
            ((float4*)sX[w][n])[r] = ((const float4*)(g_h + (size_t)(base + n) * HID_DIM))[r];
        }
        __syncwarp();
        u64 a0[8], a1[8];
        #pragma unroll
        for (int n = 0; n < 8; n++) { a0[n] = 0; a1[n] = 0; }
        #pragma unroll 8
        for (int t = 0; t < 64; t++) {
            ulonglong2 wA = *(const ulonglong2*)&sW[t * 64 + c0];
            #pragma unroll
            for (int n = 0; n < 8; n++) {
                u64 xp = *(const u64*)&sX[w][n][2 * t];
                fma2(a0[n], xp, wA.x); fma2(a1[n], xp, wA.y);
            }
        }
        #pragma unroll
        for (int n = 0; n < 8; n++) {
            float2 f0 = unpk(a0[n]), f1 = unpk(a1[n]);
            ((float2*)(g_hw + (size_t)(base + n) * OUT_DIM))[lane] =
                make_float2(f0.x + f0.y, f1.x + f1.y);
        }
        __syncwarp();
    }
}

// ---------------- Aggregation 2: out = A_norm @ hw + b2 ----------------
__global__ __launch_bounds__(256) void k_agg2(const float* __restrict__ b2,
                                              float* __restrict__ out) {
    int gw   = (blockIdx.x * blockDim.x + threadIdx.x) >> 5;
    int lane = threadIdx.x & 31;
    if (gw >= N_NODES) return;
    float di = g_dinv[gw];
    int deg = g_cnt[gw]; if (deg > CAP) deg = CAP;
    float2 bv = ((const float2*)b2)[lane];
    u64 acc = pk(bv.x, bv.y);
    fma2(acc, dup2(di * di), ((const u64*)g_hw)[gw * 32 + lane]);
    acc = agg_gather(g_hw, gw * CAP, gw * CAP + deg, di, lane, acc);
    ((u64*)out)[gw * 32 + lane] = acc;
}

// ---------------- launch ----------------
extern "C" void kernel_launch(void* const* d_in, const int* in_sizes, int n_in,
                              void* d_out, int out_size) {
    const float* z  = nullptr;
    const int*   ei = nullptr;
    const float* W1 = nullptr;
    const float* W2 = nullptr;
    const float* b1 = nullptr;
    const float* b2 = nullptr;
    for (int i = 0; i < n_in; i++) {
        int n = in_sizes[i];
        if      (n == N_NODES * IN_DIM)  z  = (const float*)d_in[i];
        else if (n == 2 * N_EDGES)       ei = (const int*)d_in[i];
        else if (n == IN_DIM * HID_DIM) { if (!W1) W1 = (const float*)d_in[i]; else W2 = (const float*)d_in[i]; }
        else if (n == HID_DIM)           b1 = (const float*)d_in[i];
        else if (n == OUT_DIM)           b2 = (const float*)d_in[i];
    }
    float* out = (float*)d_out;

    const int gN  = (N_NODES + 255) / 256;
    const int gE  = (N_EDGES + 255) / 256;
    const int gW  = (N_NODES * 32 + 255) / 256;
    const int gG  = 1563;

    k_init   <<<gN, 256>>>();
    k_scatter<<<gE, 256>>>(ei);
    k_dinv   <<<gN, 256>>>();

    k_aggz <<<gW, 256>>>(z);
    k_gemm1<<<gG, 128>>>(W1, b1);
    k_gemm2<<<gG, 128>>>(W2);
    k_agg2 <<<gW, 256>>>(b2, out);
}

// round 8
// speedup vs baseline: 1.3011x; 1.3011x over previous
#include <cuda_runtime.h>
#include <cuda_bf16.h>

#define N_NODES 50000
#define N_EDGES 800000
#define IN_DIM  64
#define HID_DIM 128
#define OUT_DIM 64

typedef unsigned long long u64;

// ---------------- packed f32x2 helpers (Blackwell FFMA2) ----------------
__device__ __forceinline__ u64 pk(float x, float y) {
    u64 r; asm("mov.b64 %0, {%1, %2};" : "=l"(r) : "f"(x), "f"(y)); return r;
}
__device__ __forceinline__ u64 dup2(float x) {
    u64 r; asm("mov.b64 %0, {%1, %2};" : "=l"(r) : "f"(x), "f"(x)); return r;
}
__device__ __forceinline__ void fma2(u64& d, u64 a, u64 b) {
    asm("fma.rn.f32x2 %0, %1, %2, %3;" : "=l"(d) : "l"(a), "l"(b), "l"(d));
}
__device__ __forceinline__ float2 unpk(u64 a) {
    float2 f; asm("mov.b64 {%0, %1}, %2;" : "=f"(f.x), "=f"(f.y) : "l"(a)); return f;
}

// ---------------- scratch ----------------
__device__ __align__(16) float g_az[N_NODES * IN_DIM];
__device__ __align__(16) float g_h [N_NODES * HID_DIM];
__device__ __align__(16) float g_hw[N_NODES * OUT_DIM];
__device__ float g_dinv[N_NODES];
__device__ int   g_cnt[N_NODES];
__device__ int   g_cur[N_NODES];
__device__ int   g_rowptr[N_NODES + 1];
__device__ u64   g_ew[N_EDGES];            // packed {src id (lo), dinv[src] (hi)}
__device__ int   g_lb[64];

// ---------------- init ----------------
__global__ void k_init() {
    int i = blockIdx.x * blockDim.x + threadIdx.x;
    if (i < N_NODES) g_cnt[i] = 0;
    if (i < 64) g_lb[i] = 0;
}

__global__ void k_count(const int* __restrict__ ei) {
    int e = blockIdx.x * blockDim.x + threadIdx.x;
    if (e < N_EDGES) atomicAdd(&g_cnt[ei[N_EDGES + e]], 1);
}

// ---------------- decoupled-lookback scan + dinv + cursors (shfl version) ----------------
__global__ __launch_bounds__(1024) void k_scanlb() {
    __shared__ int wtot[32];
    __shared__ int s_prefix;
    int b = blockIdx.x, t = threadIdx.x;
    int lane = t & 31, wid = t >> 5;
    int i = b * 1024 + t;
    int v = (i < N_NODES) ? g_cnt[i] : 0;

    int s = v;
    #pragma unroll
    for (int off = 1; off < 32; off <<= 1) {
        int tv = __shfl_up_sync(0xffffffff, s, off);
        if (lane >= off) s += tv;
    }
    if (lane == 31) wtot[wid] = s;
    __syncthreads();
    if (wid == 0) {
        int wv = wtot[lane];
        int ws = wv;
        #pragma unroll
        for (int off = 1; off < 32; off <<= 1) {
            int tv = __shfl_up_sync(0xffffffff, ws, off);
            if (lane >= off) ws += tv;
        }
        wtot[lane] = ws - wv;
        if (lane == 31) {
            int total = ws;
            if (b > 0) atomicExch(&g_lb[b], (1 << 28) | total);
            int prefix = 0;
            for (int j = b - 1; j >= 0; ) {
                int f = atomicAdd(&g_lb[j], 0);
                int st = f >> 28;
                if (st == 2) { prefix += f & 0x0FFFFFFF; break; }
                if (st == 1) { prefix += f & 0x0FFFFFFF; j--; }
            }
            atomicExch(&g_lb[b], (2 << 28) | (prefix + total));
            s_prefix = prefix;
        }
    }
    __syncthreads();
    if (i < N_NODES) {
        int incl = s + wtot[wid] + s_prefix;
        g_rowptr[i + 1] = incl;
        g_cur[i] = incl - v;
        g_dinv[i] = rsqrtf((float)(v + 1));
    }
    if (i == 0) g_rowptr[0] = 0;
}

// scatter: emit packed {src, dinv[src]} (dinv is ready — scanlb ran first)
__global__ void k_scatter(const int* __restrict__ ei) {
    int e = blockIdx.x * blockDim.x + threadIdx.x;
    if (e < N_EDGES) {
        int s = ei[e];
        int d = ei[N_EDGES + e];
        float w = __ldg(&g_dinv[s]);
        int pos = atomicAdd(&g_cur[d], 1);
        g_ew[pos] = pk(__int_as_float(s), w);   // lo = id bits, hi = w
    }
}

// ---------------- gather-accumulate: acc += sum_e dinv[s_e] * row[s_e] ----------------
__device__ __forceinline__ u64 agg_gather(const float* __restrict__ src,
                                          int beg, int end, int lane, u64 acc) {
    int e = beg;
    for (; e + 8 <= end; e += 8) {
        int2 pr[8]; u64 vv[8];
        #pragma unroll
        for (int k = 0; k < 8; k++) pr[k] = __ldg((const int2*)&g_ew[e + k]);
        #pragma unroll
        for (int k = 0; k < 8; k++) vv[k] = ((const u64*)src)[(size_t)pr[k].x * 32 + lane];
        #pragma unroll
        for (int k = 0; k < 8; k++) fma2(acc, dup2(__int_as_float(pr[k].y)), vv[k]);
    }
    for (; e + 4 <= end; e += 4) {
        int2 pr[4]; u64 vv[4];
        #pragma unroll
        for (int k = 0; k < 4; k++) pr[k] = __ldg((const int2*)&g_ew[e + k]);
        #pragma unroll
        for (int k = 0; k < 4; k++) vv[k] = ((const u64*)src)[(size_t)pr[k].x * 32 + lane];
        #pragma unroll
        for (int k = 0; k < 4; k++) fma2(acc, dup2(__int_as_float(pr[k].y)), vv[k]);
    }
    for (; e < end; e++) {
        int2 pr = __ldg((const int2*)&g_ew[e]);
        fma2(acc, dup2(__int_as_float(pr.y)), ((const u64*)src)[(size_t)pr.x * 32 + lane]);
    }
    return acc;
}

// ---------------- Aggregation 0: az = dinv_d * (sum dinv_s * z_s + dinv_d * z_d) ----------------
__global__ __launch_bounds__(256) void k_aggz(const float* __restrict__ z) {
    int gw   = (blockIdx.x * blockDim.x + threadIdx.x) >> 5;
    int lane = threadIdx.x & 31;
    if (gw >= N_NODES) return;
    float di = g_dinv[gw];
    u64 acc = 0;
    fma2(acc, dup2(di), ((const u64*)z)[gw * 32 + lane]);      // self with weight di
    acc = agg_gather(z, g_rowptr[gw], g_rowptr[gw + 1], lane, acc);
    u64 res = 0;
    fma2(res, dup2(di), acc);                                   // final scale by di
    ((u64*)g_az)[gw * 32 + lane] = res;
}

// ---------------- GEMM 1: h = relu(az @ W1 + b1), 8 nodes per warp ----------------
__global__ __launch_bounds__(128) void k_gemm1(const float* __restrict__ W1,
                                               const float* __restrict__ b1) {
    __shared__ u64 sW[32 * 128];
    __shared__ __align__(16) float sX[4][8][IN_DIM];
    int lane = threadIdx.x & 31;
    int w    = threadIdx.x >> 5;
    for (int idx = threadIdx.x; idx < 32 * 128; idx += 128) {
        int t = idx >> 7, j = idx & 127;
        sW[idx] = pk(W1[(2 * t) * 128 + j], W1[(2 * t + 1) * 128 + j]);
    }
    __syncthreads();
    int c0 = 2 * lane;
    float2 bA = *(const float2*)&b1[c0];
    float2 bB = *(const float2*)&b1[c0 + 64];

    int warpId = blockIdx.x * 4 + w;
    int nWarps = gridDim.x * 4;
    for (int base = warpId * 8; base < N_NODES; base += nWarps * 8) {
        #pragma unroll
        for (int q = 0; q < 4; q++) {
            int idx = lane + 32 * q;
            int n = idx >> 4, r = idx & 15;
            ((float4*)sX[w][n])[r] = ((const float4*)(g_az + (size_t)(base + n) * IN_DIM))[r];
        }
        __syncwarp();
        u64 aA0[8], aA1[8], aB0[8], aB1[8];
        #pragma unroll
        for (int n = 0; n < 8; n++) {
            aA0[n] = pk(bA.x, 0.f); aA1[n] = pk(bA.y, 0.f);
            aB0[n] = pk(bB.x, 0.f); aB1[n] = pk(bB.y, 0.f);
        }
        #pragma unroll 4
        for (int t = 0; t < 32; t++) {
            ulonglong2 wA = *(const ulonglong2*)&sW[t * 128 + c0];
            ulonglong2 wB = *(const ulonglong2*)&sW[t * 128 + c0 + 64];
            #pragma unroll
            for (int n = 0; n < 8; n++) {
                u64 xp = *(const u64*)&sX[w][n][2 * t];
                fma2(aA0[n], xp, wA.x); fma2(aA1[n], xp, wA.y);
                fma2(aB0[n], xp, wB.x); fma2(aB1[n], xp, wB.y);
            }
        }
        #pragma unroll
        for (int n = 0; n < 8; n++) {
            float2 f0 = unpk(aA0[n]), f1 = unpk(aA1[n]);
            float2 f2 = unpk(aB0[n]), f3 = unpk(aB1[n]);
            float* hrow = g_h + (size_t)(base + n) * HID_DIM;
            ((float2*)hrow)[lane] =
                make_float2(fmaxf(f0.x + f0.y, 0.f), fmaxf(f1.x + f1.y, 0.f));
            ((float2*)(hrow + 64))[lane] =
                make_float2(fmaxf(f2.x + f2.y, 0.f), fmaxf(f3.x + f3.y, 0.f));
        }
        __syncwarp();
    }
}

// ---------------- GEMM 2: hw = h @ W2, 8 nodes per warp ----------------
__global__ __launch_bounds__(128) void k_gemm2(const float* __restrict__ W2) {
    __shared__ u64 sW[64 * 64];
    __shared__ __align__(16) float sX[4][8][HID_DIM];
    int lane = threadIdx.x & 31;
    int w    = threadIdx.x >> 5;
    for (int idx = threadIdx.x; idx < 64 * 64; idx += 128) {
        int t = idx >> 6, j = idx & 63;
        sW[idx] = pk(W2[(2 * t) * 64 + j], W2[(2 * t + 1) * 64 + j]);
    }
    __syncthreads();
    int c0 = 2 * lane;

    int warpId = blockIdx.x * 4 + w;
    int nWarps = gridDim.x * 4;
    for (int base = warpId * 8; base < N_NODES; base += nWarps * 8) {
        #pragma unroll
        for (int q = 0; q < 8; q++) {
            int idx = lane + 32 * q;
            int n = idx >> 5, r = idx & 31;
            ((float4*)sX[w][n])[r] = ((const float4*)(g_h + (size_t)(base + n) * HID_DIM))[r];
        }
        __syncwarp();
        u64 a0[8], a1[8];
        #pragma unroll
        for (int n = 0; n < 8; n++) { a0[n] = 0; a1[n] = 0; }
        #pragma unroll 8
        for (int t = 0; t < 64; t++) {
            ulonglong2 wA = *(const ulonglong2*)&sW[t * 64 + c0];
            #pragma unroll
            for (int n = 0; n < 8; n++) {
                u64 xp = *(const u64*)&sX[w][n][2 * t];
                fma2(a0[n], xp, wA.x); fma2(a1[n], xp, wA.y);
            }
        }
        #pragma unroll
        for (int n = 0; n < 8; n++) {
            float2 f0 = unpk(a0[n]), f1 = unpk(a1[n]);
            ((float2*)(g_hw + (size_t)(base + n) * OUT_DIM))[lane] =
                make_float2(f0.x + f0.y, f1.x + f1.y);
        }
        __syncwarp();
    }
}

// ---------------- Aggregation 2: out = dinv_d*(sum dinv_s*hw_s + dinv_d*hw_d) + b2 ----------------
__global__ __launch_bounds__(256) void k_agg2(const float* __restrict__ b2,
                                              float* __restrict__ out) {
    int gw   = (blockIdx.x * blockDim.x + threadIdx.x) >> 5;
    int lane = threadIdx.x & 31;
    if (gw >= N_NODES) return;
    float di = g_dinv[gw];
    u64 acc = 0;
    fma2(acc, dup2(di), ((const u64*)g_hw)[gw * 32 + lane]);
    acc = agg_gather(g_hw, g_rowptr[gw], g_rowptr[gw + 1], lane, acc);
    float2 bv = ((const float2*)b2)[lane];
    u64 res = pk(bv.x, bv.y);
    fma2(res, dup2(di), acc);
    ((u64*)out)[gw * 32 + lane] = res;
}

// ---------------- launch ----------------
extern "C" void kernel_launch(void* const* d_in, const int* in_sizes, int n_in,
                              void* d_out, int out_size) {
    const float* z  = nullptr;
    const int*   ei = nullptr;
    const float* W1 = nullptr;
    const float* W2 = nullptr;
    const float* b1 = nullptr;
    const float* b2 = nullptr;
    for (int i = 0; i < n_in; i++) {
        int n = in_sizes[i];
        if      (n == N_NODES * IN_DIM)  z  = (const float*)d_in[i];
        else if (n == 2 * N_EDGES)       ei = (const int*)d_in[i];
        else if (n == IN_DIM * HID_DIM) { if (!W1) W1 = (const float*)d_in[i]; else W2 = (const float*)d_in[i]; }
        else if (n == HID_DIM)           b1 = (const float*)d_in[i];
        else if (n == OUT_DIM)           b2 = (const float*)d_in[i];
    }
    float* out = (float*)d_out;

    const int gN  = (N_NODES + 255) / 256;
    const int gE  = (N_EDGES + 255) / 256;
    const int gSC = (N_NODES + 1023) / 1024;
    const int gW  = (N_NODES * 32 + 255) / 256;
    const int gG  = 1563;

    k_init   <<<gN, 256>>>();
    k_count  <<<gE, 256>>>(ei);
    k_scanlb <<<gSC, 1024>>>();
    k_scatter<<<gE, 256>>>(ei);

    k_aggz <<<gW, 256>>>(z);
    k_gemm1<<<gG, 128>>>(W1, b1);
    k_gemm2<<<gG, 128>>>(W2);
    k_agg2 <<<gW, 256>>>(b2, out);
}

// round 9
// speedup vs baseline: 1.3502x; 1.0377x over previous
#include <cuda_runtime.h>
#include <cuda_bf16.h>

#define N_NODES 50000
#define N_EDGES 800000
#define IN_DIM  64
#define HID_DIM 128
#define OUT_DIM 64

typedef unsigned long long u64;

// ---------------- packed f32x2 helpers (Blackwell FFMA2/FADD2) ----------------
__device__ __forceinline__ u64 pk(float x, float y) {
    u64 r; asm("mov.b64 %0, {%1, %2};" : "=l"(r) : "f"(x), "f"(y)); return r;
}
__device__ __forceinline__ u64 dup2(float x) {
    u64 r; asm("mov.b64 %0, {%1, %2};" : "=l"(r) : "f"(x), "f"(x)); return r;
}
__device__ __forceinline__ void fma2(u64& d, u64 a, u64 b) {
    asm("fma.rn.f32x2 %0, %1, %2, %3;" : "=l"(d) : "l"(a), "l"(b), "l"(d));
}
__device__ __forceinline__ void add2(u64& d, u64 a) {
    asm("add.rn.f32x2 %0, %1, %2;" : "=l"(d) : "l"(d), "l"(a));
}
__device__ __forceinline__ float2 unpk(u64 a) {
    float2 f; asm("mov.b64 {%0, %1}, %2;" : "=f"(f.x), "=f"(f.y) : "l"(a)); return f;
}

// ---------------- scratch ----------------
__device__ __align__(16) float g_zs[N_NODES * IN_DIM];    // dinv_s * z_s
__device__ __align__(16) float g_az[N_NODES * IN_DIM];    // aggregated layer-1 input
__device__ __align__(16) float g_h [N_NODES * HID_DIM];   // relu(az @ W1 + b1)
__device__ __align__(16) float g_hw[N_NODES * OUT_DIM];   // dinv_s * (h @ W2)
__device__ float g_dinv[N_NODES];
__device__ int   g_cnt[N_NODES];
__device__ int   g_cur[N_NODES];
__device__ int   g_rowptr[N_NODES + 1];
__device__ int   g_esrc[N_EDGES];
__device__ int   g_lb[64];

// ---------------- init ----------------
__global__ void k_init() {
    int i = blockIdx.x * blockDim.x + threadIdx.x;
    if (i < N_NODES) g_cnt[i] = 0;
    if (i < 64) g_lb[i] = 0;
}

__global__ void k_count(const int* __restrict__ ei) {
    int e = blockIdx.x * blockDim.x + threadIdx.x;
    if (e < N_EDGES) atomicAdd(&g_cnt[ei[N_EDGES + e]], 1);
}

// ---------------- decoupled-lookback scan + dinv + cursors ----------------
__global__ __launch_bounds__(1024) void k_scanlb() {
    __shared__ int wtot[32];
    __shared__ int s_prefix;
    int b = blockIdx.x, t = threadIdx.x;
    int lane = t & 31, wid = t >> 5;
    int i = b * 1024 + t;
    int v = (i < N_NODES) ? g_cnt[i] : 0;

    int s = v;
    #pragma unroll
    for (int off = 1; off < 32; off <<= 1) {
        int tv = __shfl_up_sync(0xffffffff, s, off);
        if (lane >= off) s += tv;
    }
    if (lane == 31) wtot[wid] = s;
    __syncthreads();
    if (wid == 0) {
        int wv = wtot[lane];
        int ws = wv;
        #pragma unroll
        for (int off = 1; off < 32; off <<= 1) {
            int tv = __shfl_up_sync(0xffffffff, ws, off);
            if (lane >= off) ws += tv;
        }
        wtot[lane] = ws - wv;
        if (lane == 31) {
            int total = ws;
            if (b > 0) atomicExch(&g_lb[b], (1 << 28) | total);
            int prefix = 0;
            for (int j = b - 1; j >= 0; ) {
                int f = atomicAdd(&g_lb[j], 0);
                int st = f >> 28;
                if (st == 2) { prefix += f & 0x0FFFFFFF; break; }
                if (st == 1) { prefix += f & 0x0FFFFFFF; j--; }
            }
            atomicExch(&g_lb[b], (2 << 28) | (prefix + total));
            s_prefix = prefix;
        }
    }
    __syncthreads();
    if (i < N_NODES) {
        int incl = s + wtot[wid] + s_prefix;
        g_rowptr[i + 1] = incl;
        g_cur[i] = incl - v;
        g_dinv[i] = rsqrtf((float)(v + 1));
    }
    if (i == 0) g_rowptr[0] = 0;
}

__global__ void k_scatter(const int* __restrict__ ei) {
    int e = blockIdx.x * blockDim.x + threadIdx.x;
    if (e < N_EDGES) {
        int s = ei[e];
        int d = ei[N_EDGES + e];
        int pos = atomicAdd(&g_cur[d], 1);
        g_esrc[pos] = s;
    }
}

// ---------------- zs = dinv * z  (thread per f32x2 pair) ----------------
__global__ void k_zscale(const float* __restrict__ z) {
    int idx = blockIdx.x * blockDim.x + threadIdx.x;   // over N_NODES*32 u64s
    if (idx < N_NODES * 32) {
        float dv = g_dinv[idx >> 5];
        u64 r = 0;
        fma2(r, dup2(dv), ((const u64*)z)[idx]);
        ((u64*)g_zs)[idx] = r;
    }
}

// ---------------- gather-accumulate: acc += sum_e row[s_e]  (pure FADD2) ----------------
__device__ __forceinline__ u64 agg_gather(const float* __restrict__ src,
                                          int beg, int end, int lane, u64 acc) {
    int e = beg;
    for (; e + 8 <= end; e += 8) {
        int id[8]; u64 vv[8];
        #pragma unroll
        for (int k = 0; k < 8; k++) id[k] = __ldg(&g_esrc[e + k]);
        #pragma unroll
        for (int k = 0; k < 8; k++) vv[k] = ((const u64*)src)[(unsigned)(id[k] * 32 + lane)];
        #pragma unroll
        for (int k = 0; k < 8; k++) add2(acc, vv[k]);
    }
    for (; e + 4 <= end; e += 4) {
        int id[4]; u64 vv[4];
        #pragma unroll
        for (int k = 0; k < 4; k++) id[k] = __ldg(&g_esrc[e + k]);
        #pragma unroll
        for (int k = 0; k < 4; k++) vv[k] = ((const u64*)src)[(unsigned)(id[k] * 32 + lane)];
        #pragma unroll
        for (int k = 0; k < 4; k++) add2(acc, vv[k]);
    }
    for (; e < end; e++) {
        int s = __ldg(&g_esrc[e]);
        add2(acc, ((const u64*)src)[(unsigned)(s * 32 + lane)]);
    }
    return acc;
}

// ---------------- Aggregation 0: az = dinv_d * (sum zs[s] + zs[d]) ----------------
__global__ __launch_bounds__(256) void k_aggz() {
    int gw   = (blockIdx.x * blockDim.x + threadIdx.x) >> 5;
    int lane = threadIdx.x & 31;
    if (gw >= N_NODES) return;
    float di = g_dinv[gw];
    u64 acc = ((const u64*)g_zs)[gw * 32 + lane];          // self (already dinv_d-scaled once)
    acc = agg_gather(g_zs, g_rowptr[gw], g_rowptr[gw + 1], lane, acc);
    u64 res = 0;
    fma2(res, dup2(di), acc);
    ((u64*)g_az)[gw * 32 + lane] = res;
}

// ---------------- GEMM 1: h = relu(az @ W1 + b1), 8 nodes per warp ----------------
__global__ __launch_bounds__(128) void k_gemm1(const float* __restrict__ W1,
                                               const float* __restrict__ b1) {
    __shared__ u64 sW[32 * 128];
    __shared__ __align__(16) float sX[4][8][IN_DIM];
    int lane = threadIdx.x & 31;
    int w    = threadIdx.x >> 5;
    for (int idx = threadIdx.x; idx < 32 * 128; idx += 128) {
        int t = idx >> 7, j = idx & 127;
        sW[idx] = pk(W1[(2 * t) * 128 + j], W1[(2 * t + 1) * 128 + j]);
    }
    __syncthreads();
    int c0 = 2 * lane;
    float2 bA = *(const float2*)&b1[c0];
    float2 bB = *(const float2*)&b1[c0 + 64];

    int warpId = blockIdx.x * 4 + w;
    int nWarps = gridDim.x * 4;
    for (int base = warpId * 8; base < N_NODES; base += nWarps * 8) {
        #pragma unroll
        for (int q = 0; q < 4; q++) {
            int idx = lane + 32 * q;
            int n = idx >> 4, r = idx & 15;
            ((float4*)sX[w][n])[r] = ((const float4*)(g_az + (size_t)(base + n) * IN_DIM))[r];
        }
        __syncwarp();
        u64 aA0[8], aA1[8], aB0[8], aB1[8];
        #pragma unroll
        for (int n = 0; n < 8; n++) {
            aA0[n] = pk(bA.x, 0.f); aA1[n] = pk(bA.y, 0.f);
            aB0[n] = pk(bB.x, 0.f); aB1[n] = pk(bB.y, 0.f);
        }
        #pragma unroll 4
        for (int t = 0; t < 32; t++) {
            ulonglong2 wA = *(const ulonglong2*)&sW[t * 128 + c0];
            ulonglong2 wB = *(const ulonglong2*)&sW[t * 128 + c0 + 64];
            #pragma unroll
            for (int n = 0; n < 8; n++) {
                u64 xp = *(const u64*)&sX[w][n][2 * t];
                fma2(aA0[n], xp, wA.x); fma2(aA1[n], xp, wA.y);
                fma2(aB0[n], xp, wB.x); fma2(aB1[n], xp, wB.y);
            }
        }
        #pragma unroll
        for (int n = 0; n < 8; n++) {
            float2 f0 = unpk(aA0[n]), f1 = unpk(aA1[n]);
            float2 f2 = unpk(aB0[n]), f3 = unpk(aB1[n]);
            float* hrow = g_h + (size_t)(base + n) * HID_DIM;
            ((float2*)hrow)[lane] =
                make_float2(fmaxf(f0.x + f0.y, 0.f), fmaxf(f1.x + f1.y, 0.f));
            ((float2*)(hrow + 64))[lane] =
                make_float2(fmaxf(f2.x + f2.y, 0.f), fmaxf(f3.x + f3.y, 0.f));
        }
        __syncwarp();
    }
}

// ---------------- GEMM 2: hw = dinv * (h @ W2), 8 nodes per warp ----------------
__global__ __launch_bounds__(128) void k_gemm2(const float* __restrict__ W2) {
    __shared__ u64 sW[64 * 64];
    __shared__ __align__(16) float sX[4][8][HID_DIM];
    int lane = threadIdx.x & 31;
    int w    = threadIdx.x >> 5;
    for (int idx = threadIdx.x; idx < 64 * 64; idx += 128) {
        int t = idx >> 6, j = idx & 63;
        sW[idx] = pk(W2[(2 * t) * 64 + j], W2[(2 * t + 1) * 64 + j]);
    }
    __syncthreads();
    int c0 = 2 * lane;

    int warpId = blockIdx.x * 4 + w;
    int nWarps = gridDim.x * 4;
    for (int base = warpId * 8; base < N_NODES; base += nWarps * 8) {
        #pragma unroll
        for (int q = 0; q < 8; q++) {
            int idx = lane + 32 * q;
            int n = idx >> 5, r = idx & 31;
            ((float4*)sX[w][n])[r] = ((const float4*)(g_h + (size_t)(base + n) * HID_DIM))[r];
        }
        __syncwarp();
        u64 a0[8], a1[8];
        #pragma unroll
        for (int n = 0; n < 8; n++) { a0[n] = 0; a1[n] = 0; }
        #pragma unroll 8
        for (int t = 0; t < 64; t++) {
            ulonglong2 wA = *(const ulonglong2*)&sW[t * 64 + c0];
            #pragma unroll
            for (int n = 0; n < 8; n++) {
                u64 xp = *(const u64*)&sX[w][n][2 * t];
                fma2(a0[n], xp, wA.x); fma2(a1[n], xp, wA.y);
            }
        }
        #pragma unroll
        for (int n = 0; n < 8; n++) {
            float dv = __ldg(&g_dinv[base + n]);            // fold dinv_s scaling here
            float2 f0 = unpk(a0[n]), f1 = unpk(a1[n]);
            ((float2*)(g_hw + (size_t)(base + n) * OUT_DIM))[lane] =
                make_float2(dv * (f0.x + f0.y), dv * (f1.x + f1.y));
        }
        __syncwarp();
    }
}

// ---------------- Aggregation 2: out = dinv_d * (sum hw[s] + hw[d]) + b2 ----------------
__global__ __launch_bounds__(256) void k_agg2(const float* __restrict__ b2,
                                              float* __restrict__ out) {
    int gw   = (blockIdx.x * blockDim.x + threadIdx.x) >> 5;
    int lane = threadIdx.x & 31;
    if (gw >= N_NODES) return;
    float di = g_dinv[gw];
    u64 acc = ((const u64*)g_hw)[gw * 32 + lane];           // self
    acc = agg_gather(g_hw, g_rowptr[gw], g_rowptr[gw + 1], lane, acc);
    float2 bv = ((const float2*)b2)[lane];
    u64 res = pk(bv.x, bv.y);
    fma2(res, dup2(di), acc);
    ((u64*)out)[gw * 32 + lane] = res;
}

// ---------------- launch ----------------
extern "C" void kernel_launch(void* const* d_in, const int* in_sizes, int n_in,
                              void* d_out, int out_size) {
    const float* z  = nullptr;
    const int*   ei = nullptr;
    const float* W1 = nullptr;
    const float* W2 = nullptr;
    const float* b1 = nullptr;
    const float* b2 = nullptr;
    for (int i = 0; i < n_in; i++) {
        int n = in_sizes[i];
        if      (n == N_NODES * IN_DIM)  z  = (const float*)d_in[i];
        else if (n == 2 * N_EDGES)       ei = (const int*)d_in[i];
        else if (n == IN_DIM * HID_DIM) { if (!W1) W1 = (const float*)d_in[i]; else W2 = (const float*)d_in[i]; }
        else if (n == HID_DIM)           b1 = (const float*)d_in[i];
        else if (n == OUT_DIM)           b2 = (const float*)d_in[i];
    }
    float* out = (float*)d_out;

    const int gN  = (N_NODES + 255) / 256;
    const int gE  = (N_EDGES + 255) / 256;
    const int gSC = (N_NODES + 1023) / 1024;
    const int gW  = (N_NODES * 32 + 255) / 256;
    const int gZ  = (N_NODES * 32 + 255) / 256;
    const int gG  = 1563;

    k_init   <<<gN, 256>>>();
    k_count  <<<gE, 256>>>(ei);
    k_scanlb <<<gSC, 1024>>>();
    k_zscale <<<gZ, 256>>>(z);     // after scanlb (needs dinv); independent of scatter
    k_scatter<<<gE, 256>>>(ei);

    k_aggz <<<gW, 256>>>();
    k_gemm1<<<gG, 128>>>(W1, b1);
    k_gemm2<<<gG, 128>>>(W2);
    k_agg2 <<<gW, 256>>>(b2, out);
}

// round 10
// speedup vs baseline: 1.4072x; 1.0422x over previous
#include <cuda_runtime.h>
#include <cuda_bf16.h>

#define N_NODES 50000
#define N_EDGES 800000
#define IN_DIM  64
#define HID_DIM 128
#define OUT_DIM 64

typedef unsigned long long u64;

// ---------------- packed f32x2 helpers (Blackwell FFMA2/FADD2) ----------------
__device__ __forceinline__ u64 pk(float x, float y) {
    u64 r; asm("mov.b64 %0, {%1, %2};" : "=l"(r) : "f"(x), "f"(y)); return r;
}
__device__ __forceinline__ u64 dup2(float x) {
    u64 r; asm("mov.b64 %0, {%1, %2};" : "=l"(r) : "f"(x), "f"(x)); return r;
}
__device__ __forceinline__ void fma2(u64& d, u64 a, u64 b) {
    asm("fma.rn.f32x2 %0, %1, %2, %3;" : "=l"(d) : "l"(a), "l"(b), "l"(d));
}
__device__ __forceinline__ void add2(u64& d, u64 a) {
    asm("add.rn.f32x2 %0, %1, %2;" : "=l"(d) : "l"(d), "l"(a));
}
__device__ __forceinline__ float2 unpk(u64 a) {
    float2 f; asm("mov.b64 {%0, %1}, %2;" : "=f"(f.x), "=f"(f.y) : "l"(a)); return f;
}

// ---------------- scratch ----------------
__device__ __align__(16) float g_zs[N_NODES * IN_DIM];    // dinv_s * z_s
__device__ __align__(16) float g_az[N_NODES * IN_DIM];    // aggregated layer-1 input
__device__ __align__(16) float g_h [N_NODES * HID_DIM];   // relu(az @ W1 + b1)
__device__ __align__(16) float g_hw[N_NODES * OUT_DIM];   // dinv_s * (h @ W2)
__device__ float g_dinv[N_NODES];
__device__ int   g_cnt[N_NODES];     // zero-init; self-cleaned by k_scanlb each call
__device__ int   g_cur[N_NODES];
__device__ int   g_rowptr[N_NODES + 1];
__device__ int   g_esrc[N_EDGES];
__device__ int   g_lb[64];           // zero-init; self-cleaned by k_scatter_zscale each call

// ---------------- count (g_cnt is 0 on entry: invariant maintained by scanlb) ----------------
__global__ void k_count(const int* __restrict__ ei) {
    int e = blockIdx.x * blockDim.x + threadIdx.x;
    if (e < N_EDGES) atomicAdd(&g_cnt[ei[N_EDGES + e]], 1);
}

// ---------------- decoupled-lookback scan + dinv + cursors; resets g_cnt ----------------
__global__ __launch_bounds__(1024) void k_scanlb() {
    __shared__ int wtot[32];
    __shared__ int s_prefix;
    int b = blockIdx.x, t = threadIdx.x;
    int lane = t & 31, wid = t >> 5;
    int i = b * 1024 + t;
    int v = (i < N_NODES) ? g_cnt[i] : 0;

    int s = v;
    #pragma unroll
    for (int off = 1; off < 32; off <<= 1) {
        int tv = __shfl_up_sync(0xffffffff, s, off);
        if (lane >= off) s += tv;
    }
    if (lane == 31) wtot[wid] = s;
    __syncthreads();
    if (wid == 0) {
        int wv = wtot[lane];
        int ws = wv;
        #pragma unroll
        for (int off = 1; off < 32; off <<= 1) {
            int tv = __shfl_up_sync(0xffffffff, ws, off);
            if (lane >= off) ws += tv;
        }
        wtot[lane] = ws - wv;
        if (lane == 31) {
            int total = ws;
            if (b > 0) atomicExch(&g_lb[b], (1 << 28) | total);
            int prefix = 0;
            for (int j = b - 1; j >= 0; ) {
                int f = atomicAdd(&g_lb[j], 0);
                int st = f >> 28;
                if (st == 2) { prefix += f & 0x0FFFFFFF; break; }
                if (st == 1) { prefix += f & 0x0FFFFFFF; j--; }
            }
            atomicExch(&g_lb[b], (2 << 28) | (prefix + total));
            s_prefix = prefix;
        }
    }
    __syncthreads();
    if (i < N_NODES) {
        int incl = s + wtot[wid] + s_prefix;
        g_rowptr[i + 1] = incl;
        g_cur[i] = incl - v;
        g_dinv[i] = rsqrtf((float)(v + 1));
        g_cnt[i] = 0;                      // restore invariant for next graph replay
    }
    if (i == 0) g_rowptr[0] = 0;
}

// ---------------- merged: scatter (blocks [0,GE)) + zscale (blocks [GE,GE+GZ)) ----------------
#define GE_BLOCKS 3125   // ceil(800000/256)
#define GZ_BLOCKS 6250   // ceil(50000*32/256)
__global__ void k_scatter_zscale(const int* __restrict__ ei, const float* __restrict__ z) {
    int b = blockIdx.x;
    int t = threadIdx.x;
    if (b < GE_BLOCKS) {
        int e = b * 256 + t;
        if (e < N_EDGES) {
            int s = ei[e];
            int d = ei[N_EDGES + e];
            int pos = atomicAdd(&g_cur[d], 1);
            g_esrc[pos] = s;
        }
        if (b == 0 && t < 64) g_lb[t] = 0;   // restore invariant for next replay
    } else {
        int idx = (b - GE_BLOCKS) * 256 + t;  // over N_NODES*32 u64s
        if (idx < N_NODES * 32) {
            float dv = g_dinv[idx >> 5];
            u64 r = 0;
            fma2(r, dup2(dv), ((const u64*)z)[idx]);
            ((u64*)g_zs)[idx] = r;
        }
    }
}

// ---------------- gather-accumulate: acc += sum_e row[s_e]  (pure FADD2) ----------------
__device__ __forceinline__ u64 agg_gather(const float* __restrict__ src,
                                          int beg, int end, int lane, u64 acc) {
    int e = beg;
    for (; e + 8 <= end; e += 8) {
        int id[8]; u64 vv[8];
        #pragma unroll
        for (int k = 0; k < 8; k++) id[k] = __ldg(&g_esrc[e + k]);
        #pragma unroll
        for (int k = 0; k < 8; k++) vv[k] = ((const u64*)src)[(unsigned)(id[k] * 32 + lane)];
        #pragma unroll
        for (int k = 0; k < 8; k++) add2(acc, vv[k]);
    }
    for (; e + 4 <= end; e += 4) {
        int id[4]; u64 vv[4];
        #pragma unroll
        for (int k = 0; k < 4; k++) id[k] = __ldg(&g_esrc[e + k]);
        #pragma unroll
        for (int k = 0; k < 4; k++) vv[k] = ((const u64*)src)[(unsigned)(id[k] * 32 + lane)];
        #pragma unroll
        for (int k = 0; k < 4; k++) add2(acc, vv[k]);
    }
    for (; e < end; e++) {
        int s = __ldg(&g_esrc[e]);
        add2(acc, ((const u64*)src)[(unsigned)(s * 32 + lane)]);
    }
    return acc;
}

// ---------------- Aggregation 0: az = dinv_d * (sum zs[s] + zs[d]) ----------------
__global__ __launch_bounds__(256) void k_aggz() {
    int gw   = (blockIdx.x * blockDim.x + threadIdx.x) >> 5;
    int lane = threadIdx.x & 31;
    if (gw >= N_NODES) return;
    float di = g_dinv[gw];
    u64 acc = ((const u64*)g_zs)[gw * 32 + lane];
    acc = agg_gather(g_zs, g_rowptr[gw], g_rowptr[gw + 1], lane, acc);
    u64 res = 0;
    fma2(res, dup2(di), acc);
    ((u64*)g_az)[gw * 32 + lane] = res;
}

// ---------------- GEMM 1: h = relu(az @ W1 + b1), 8 nodes per warp ----------------
__global__ __launch_bounds__(128) void k_gemm1(const float* __restrict__ W1,
                                               const float* __restrict__ b1) {
    __shared__ u64 sW[32 * 128];
    __shared__ __align__(16) float sX[4][8][IN_DIM];
    int lane = threadIdx.x & 31;
    int w    = threadIdx.x >> 5;
    for (int idx = threadIdx.x; idx < 32 * 128; idx += 128) {
        int t = idx >> 7, j = idx & 127;
        sW[idx] = pk(W1[(2 * t) * 128 + j], W1[(2 * t + 1) * 128 + j]);
    }
    __syncthreads();
    int c0 = 2 * lane;
    float2 bA = *(const float2*)&b1[c0];
    float2 bB = *(const float2*)&b1[c0 + 64];

    int warpId = blockIdx.x * 4 + w;
    int nWarps = gridDim.x * 4;
    for (int base = warpId * 8; base < N_NODES; base += nWarps * 8) {
        #pragma unroll
        for (int q = 0; q < 4; q++) {
            int idx = lane + 32 * q;
            int n = idx >> 4, r = idx & 15;
            ((float4*)sX[w][n])[r] = ((const float4*)(g_az + (size_t)(base + n) * IN_DIM))[r];
        }
        __syncwarp();
        u64 aA0[8], aA1[8], aB0[8], aB1[8];
        #pragma unroll
        for (int n = 0; n < 8; n++) {
            aA0[n] = pk(bA.x, 0.f); aA1[n] = pk(bA.y, 0.f);
            aB0[n] = pk(bB.x, 0.f); aB1[n] = pk(bB.y, 0.f);
        }
        #pragma unroll 4
        for (int t = 0; t < 32; t++) {
            ulonglong2 wA = *(const ulonglong2*)&sW[t * 128 + c0];
            ulonglong2 wB = *(const ulonglong2*)&sW[t * 128 + c0 + 64];
            #pragma unroll
            for (int n = 0; n < 8; n++) {
                u64 xp = *(const u64*)&sX[w][n][2 * t];
                fma2(aA0[n], xp, wA.x); fma2(aA1[n], xp, wA.y);
                fma2(aB0[n], xp, wB.x); fma2(aB1[n], xp, wB.y);
            }
        }
        #pragma unroll
        for (int n = 0; n < 8; n++) {
            float2 f0 = unpk(aA0[n]), f1 = unpk(aA1[n]);
            float2 f2 = unpk(aB0[n]), f3 = unpk(aB1[n]);
            float* hrow = g_h + (size_t)(base + n) * HID_DIM;
            ((float2*)hrow)[lane] =
                make_float2(fmaxf(f0.x + f0.y, 0.f), fmaxf(f1.x + f1.y, 0.f));
            ((float2*)(hrow + 64))[lane] =
                make_float2(fmaxf(f2.x + f2.y, 0.f), fmaxf(f3.x + f3.y, 0.f));
        }
        __syncwarp();
    }
}

// ---------------- GEMM 2: hw = dinv * (h @ W2), 8 nodes per warp ----------------
__global__ __launch_bounds__(128) void k_gemm2(const float* __restrict__ W2) {
    __shared__ u64 sW[64 * 64];
    __shared__ __align__(16) float sX[4][8][HID_DIM];
    int lane = threadIdx.x & 31;
    int w    = threadIdx.x >> 5;
    for (int idx = threadIdx.x; idx < 64 * 64; idx += 128) {
        int t = idx >> 6, j = idx & 63;
        sW[idx] = pk(W2[(2 * t) * 64 + j], W2[(2 * t + 1) * 64 + j]);
    }
    __syncthreads();
    int c0 = 2 * lane;

    int warpId = blockIdx.x * 4 + w;
    int nWarps = gridDim.x * 4;
    for (int base = warpId * 8; base < N_NODES; base += nWarps * 8) {
        #pragma unroll
        for (int q = 0; q < 8; q++) {
            int idx = lane + 32 * q;
            int n = idx >> 5, r = idx & 31;
            ((float4*)sX[w][n])[r] = ((const float4*)(g_h + (size_t)(base + n) * HID_DIM))[r];
        }
        __syncwarp();
        u64 a0[8], a1[8];
        #pragma unroll
        for (int n = 0; n < 8; n++) { a0[n] = 0; a1[n] = 0; }
        #pragma unroll 8
        for (int t = 0; t < 64; t++) {
            ulonglong2 wA = *(const ulonglong2*)&sW[t * 64 + c0];
            #pragma unroll
            for (int n = 0; n < 8; n++) {
                u64 xp = *(const u64*)&sX[w][n][2 * t];
                fma2(a0[n], xp, wA.x); fma2(a1[n], xp, wA.y);
            }
        }
        #pragma unroll
        for (int n = 0; n < 8; n++) {
            float dv = __ldg(&g_dinv[base + n]);
            float2 f0 = unpk(a0[n]), f1 = unpk(a1[n]);
            ((float2*)(g_hw + (size_t)(base + n) * OUT_DIM))[lane] =
                make_float2(dv * (f0.x + f0.y), dv * (f1.x + f1.y));
        }
        __syncwarp();
    }
}

// ---------------- Aggregation 2: out = dinv_d * (sum hw[s] + hw[d]) + b2 ----------------
__global__ __launch_bounds__(256) void k_agg2(const float* __restrict__ b2,
                                              float* __restrict__ out) {
    int gw   = (blockIdx.x * blockDim.x + threadIdx.x) >> 5;
    int lane = threadIdx.x & 31;
    if (gw >= N_NODES) return;
    float di = g_dinv[gw];
    u64 acc = ((const u64*)g_hw)[gw * 32 + lane];
    acc = agg_gather(g_hw, g_rowptr[gw], g_rowptr[gw + 1], lane, acc);
    float2 bv = ((const float2*)b2)[lane];
    u64 res = pk(bv.x, bv.y);
    fma2(res, dup2(di), acc);
    ((u64*)out)[gw * 32 + lane] = res;
}

// ---------------- launch ----------------
extern "C" void kernel_launch(void* const* d_in, const int* in_sizes, int n_in,
                              void* d_out, int out_size) {
    const float* z  = nullptr;
    const int*   ei = nullptr;
    const float* W1 = nullptr;
    const float* W2 = nullptr;
    const float* b1 = nullptr;
    const float* b2 = nullptr;
    for (int i = 0; i < n_in; i++) {
        int n = in_sizes[i];
        if      (n == N_NODES * IN_DIM)  z  = (const float*)d_in[i];
        else if (n == 2 * N_EDGES)       ei = (const int*)d_in[i];
        else if (n == IN_DIM * HID_DIM) { if (!W1) W1 = (const float*)d_in[i]; else W2 = (const float*)d_in[i]; }
        else if (n == HID_DIM)           b1 = (const float*)d_in[i];
        else if (n == OUT_DIM)           b2 = (const float*)d_in[i];
    }
    float* out = (float*)d_out;

    const int gE  = GE_BLOCKS;
    const int gSC = (N_NODES + 1023) / 1024;
    const int gW  = (N_NODES * 32 + 255) / 256;
    const int gG  = 1563;

    k_count        <<<gE, 256>>>(ei);
    k_scanlb       <<<gSC, 1024>>>();
    k_scatter_zscale<<<GE_BLOCKS + GZ_BLOCKS, 256>>>(ei, z);

    k_aggz <<<gW, 256>>>();
    k_gemm1<<<gG, 128>>>(W1, b1);
    k_gemm2<<<gG, 128>>>(W2);
    k_agg2 <<<gW, 256>>>(b2, out);
}